// round 16
// baseline (speedup 1.0000x reference)
#include <cuda_runtime.h>
#include <cuda_bf16.h>
#include <cstdint>

// Problem: x[16,512,32,32], Q/K/V[512,512]
#define B_ 16
#define C_ 512
#define S_ 1024
#define BS_ (B_ * S_)   // 16384

typedef __nv_bfloat16 bf16;

// ---------------- device scratch ----------------
__device__ float g_xn[BS_ * C_];          // normalized x (residual)
__device__ float g_sc[B_ * S_ * S_];      // scores fp32 [B][q][k]
__device__ float g_mean[C_], g_rsig[C_];

#define PAIR(name, n) \
  __device__ __align__(16) bf16 name##h[n]; \
  __device__ __align__(16) bf16 name##l[n]
PAIR(g_xb, BS_ * C_);      // xn split       [s][c]
PAIR(g_qn, C_ * C_);       // Q natural split [a][d]
PAIR(g_kn, C_ * C_);       // K natural split [b][d]
PAIR(g_pt, C_ * C_);       // P^T split      [b][a],  P = Q@K^T/sqrt(C)
PAIR(g_vw, C_ * C_);       // V^T split      [d][c]
PAIR(g_yb, BS_ * C_);      // y = xn@P split [b*S+s][d]
PAIR(g_vt, C_ * BS_);      // v^T split      [c][b*S+s]
PAIR(g_wt, B_ * S_ * S_);  // attn weights   [b][q][j]

// ---------------- helpers ----------------
__device__ __forceinline__ void split2(float x, bf16& h, bf16& l) {
    h = __float2bfloat16(x);
    l = __float2bfloat16(x - __bfloat162float(h));
}
__device__ __forceinline__ uint32_t smem_u32(const void* p) {
    return (uint32_t)__cvta_generic_to_shared(p);
}
__device__ __forceinline__ void cp16(uint32_t dst, const void* src) {
    asm volatile("cp.async.cg.shared.global [%0], [%1], 16;" :: "r"(dst), "l"(src));
}
__device__ __forceinline__ void ldsm4(uint32_t& r0, uint32_t& r1,
                                      uint32_t& r2, uint32_t& r3, uint32_t a) {
    asm volatile("ldmatrix.sync.aligned.m8n8.x4.shared.b16 {%0,%1,%2,%3}, [%4];"
                 : "=r"(r0), "=r"(r1), "=r"(r2), "=r"(r3) : "r"(a));
}
__device__ __forceinline__ void mma16816(float* d, const uint32_t* a,
                                         uint32_t b0, uint32_t b1) {
    asm("mma.sync.aligned.m16n8k16.row.col.f32.bf16.bf16.f32 "
        "{%0,%1,%2,%3}, {%4,%5,%6,%7}, {%8,%9}, {%0,%1,%2,%3};"
        : "+f"(d[0]), "+f"(d[1]), "+f"(d[2]), "+f"(d[3])
        : "r"(a[0]), "r"(a[1]), "r"(a[2]), "r"(a[3]), "r"(b0), "r"(b1));
}

// ---------------- BatchNorm stats ----------------
__global__ __launch_bounds__(256) void bn_stats_kernel(const float* __restrict__ x) {
    int c = blockIdx.x, t = threadIdx.x;
    float s = 0.f, ss = 0.f;
    for (int b = 0; b < B_; ++b) {
        const float* p = x + ((size_t)b * C_ + c) * S_;
        for (int i = t; i < S_; i += 256) { float v = p[i]; s += v; ss += v * v; }
    }
    #pragma unroll
    for (int o = 16; o > 0; o >>= 1) {
        s  += __shfl_down_sync(0xffffffffu, s,  o);
        ss += __shfl_down_sync(0xffffffffu, ss, o);
    }
    __shared__ float shs[8], shq[8];
    int w = t >> 5, l = t & 31;
    if (l == 0) { shs[w] = s; shq[w] = ss; }
    __syncthreads();
    if (t == 0) {
        float S = 0.f, Qq = 0.f;
        #pragma unroll
        for (int i = 0; i < 8; ++i) { S += shs[i]; Qq += shq[i]; }
        const float invN = 1.0f / (float)BS_;
        float mu = S * invN;
        g_mean[c] = mu;
        g_rsig[c] = rsqrtf(Qq * invN - mu * mu + 1e-5f);
    }
}

// ---------- normalize + transpose: fp32 xn AND bf16 split pair ----------
__global__ __launch_bounds__(256) void normalize_kernel(const float* __restrict__ x) {
    __shared__ float tile[32][33];
    int b = blockIdx.z, c0 = blockIdx.y * 32, s0 = blockIdx.x * 32;
    int tx = threadIdx.x, ty = threadIdx.y;
    #pragma unroll
    for (int r = 0; r < 4; ++r)
        tile[ty + 8 * r][tx] = x[((size_t)b * C_ + c0 + ty + 8 * r) * S_ + s0 + tx];
    __syncthreads();
    float mu = g_mean[c0 + tx], rs = g_rsig[c0 + tx];
    #pragma unroll
    for (int r = 0; r < 4; ++r) {
        int s = s0 + ty + 8 * r;
        size_t idx = ((size_t)b * S_ + s) * C_ + c0 + tx;
        float v = (tile[tx][ty + 8 * r] - mu) * rs;
        g_xn[idx] = v;
        split2(v, g_xbh[idx], g_xbl[idx]);
    }
}

// ---------- natural elementwise split, 4 floats/thread ----------
__global__ __launch_bounds__(256) void nsplit_kernel(
    const float* __restrict__ in, bf16* __restrict__ oh, bf16* __restrict__ ol)
{
    int i4 = (blockIdx.x * 256 + threadIdx.x) * 4;   // < C_*C_
    float4 v = *(const float4*)(in + i4);
    bf16 h0, l0, h1, l1, h2, l2, h3, l3;
    split2(v.x, h0, l0); split2(v.y, h1, l1);
    split2(v.z, h2, l2); split2(v.w, h3, l3);
    __nv_bfloat162 hh[2] = { __nv_bfloat162(h0, h1), __nv_bfloat162(h2, h3) };
    __nv_bfloat162 ll[2] = { __nv_bfloat162(l0, l1), __nv_bfloat162(l2, l3) };
    *(uint2*)(oh + i4) = *(const uint2*)hh;
    *(uint2*)(ol + i4) = *(const uint2*)ll;
}

// ---------- weight transpose + split: out[n][k] = in[k][n] (V only) ----------
__global__ __launch_bounds__(256) void wsplit_kernel(
    const float* __restrict__ in, bf16* __restrict__ oh, bf16* __restrict__ ol)
{
    __shared__ float t[32][33];
    int n0 = blockIdx.x * 32, k0 = blockIdx.y * 32;
    int tx = threadIdx.x, ty = threadIdx.y;
    #pragma unroll
    for (int r = 0; r < 4; ++r)
        t[ty + 8 * r][tx] = in[(size_t)(k0 + ty + 8 * r) * C_ + n0 + tx];
    __syncthreads();
    #pragma unroll
    for (int r = 0; r < 4; ++r) {
        size_t idx = (size_t)(n0 + ty + 8 * r) * C_ + k0 + tx;
        split2(t[tx][ty + 8 * r], oh[idx], ol[idx]);
    }
}

// ---------------------------------------------------------------------------
// Split-2 bf16 HMMA GEMM: D[m][n] = alpha*sum_k A[m][k]*B[n][k]
// CTA 128x128, 4 warps of 64x64, K-chunk 32 (two 16-wide k-steps reusing the
// same frag registers), cp.async double buffer (dynamic smem, 2 CTAs/SM),
// ONE __syncthreads per chunk — HALF the barrier count of the K16 version.
// EPI: 0 = split-2 bf16 out; 2 = fp32*alpha; 3 = fp32 + residual.
// ---------------------------------------------------------------------------
#define KC 32
#define LDS_T 40                           // 32 k + 8 pad (stride 80B, conflict-free)
#define TILE_BYTES (128 * LDS_T * 2)       // 10240
#define BUF_BYTES  (4 * TILE_BYTES)        // 40960
#define SMEM_DYN   (2 * BUF_BYTES)         // 81920; 2 CTAs = 160KB <= 228KB/SM

template <int EPI>
__global__ __launch_bounds__(128, 2) void mma_gemm(
    const bf16* __restrict__ Ah, const bf16* __restrict__ Al, size_t sAz, int lda,
    const bf16* __restrict__ Bh, const bf16* __restrict__ Bl, size_t sBz, int ldb,
    int K, float alpha,
    float* __restrict__ outF, const float* __restrict__ resid, size_t sOz, int ldO,
    bf16* __restrict__ Oh, bf16* __restrict__ Ol)
{
    extern __shared__ bf16 smd[];           // [2][4][128][LDS_T]

    const int tid = threadIdx.x, lane = tid & 31, w = tid >> 5;   // w: 0..3
    const int m0 = blockIdx.y * 128, n0 = blockIdx.x * 128, z = blockIdx.z;
    const int warp_m = (w >> 1) * 64, warp_n = (w & 1) * 64;

    const bf16* srcs[4] = { Ah + z * sAz, Al + z * sAz,
                            Bh + z * sBz, Bl + z * sBz };
    const int lld  = (w < 2) ? lda : ldb;
    const bf16* lsrc = srcs[w] + (size_t)((w < 2 ? m0 : n0) + lane) * lld;
    const uint32_t smb  = smem_u32(smd);
    const uint32_t ldst = smb + w * TILE_BYTES + lane * (LDS_T * 2);

    auto ISSUE = [&](int kc, int buf) {
        uint32_t d = ldst + buf * BUF_BYTES;
        const bf16* s0 = lsrc + kc;
        #pragma unroll
        for (int r = 0; r < 4; ++r) {
            const bf16* sr = s0 + (size_t)(32 * r) * lld;
            uint32_t dr = d + r * (32 * LDS_T * 2);
            cp16(dr,      sr);
            cp16(dr + 16, sr + 8);
            cp16(dr + 32, sr + 16);
            cp16(dr + 48, sr + 24);
        }
        asm volatile("cp.async.commit_group;");
    };

    const uint32_t aoff = (uint32_t)((warp_m + (lane & 15)) * LDS_T + (lane >> 4) * 8);
    const uint32_t boff = (uint32_t)((warp_n + ((lane >> 4) & 1) * 8 + (lane & 7)) * LDS_T
                                     + ((lane >> 3) & 1) * 8);

    float acc[4][8][4];
    #pragma unroll
    for (int i = 0; i < 4; ++i)
        #pragma unroll
        for (int j = 0; j < 8; ++j)
            #pragma unroll
            for (int q = 0; q < 4; ++q) acc[i][j][q] = 0.f;

    const int nch = K / KC;
    ISSUE(0, 0);
    for (int t = 0; t < nch; ++t) {
        const int buf = t & 1;
        asm volatile("cp.async.wait_group 0;");
        __syncthreads();                       // chunk t visible; buf^1 free
        if (t + 1 < nch) ISSUE((t + 1) * KC, buf ^ 1);

        const uint32_t base = smb + buf * BUF_BYTES;
        #pragma unroll
        for (int ks = 0; ks < 2; ++ks) {       // two 16-wide k-steps per chunk
            const uint32_t ko = (uint32_t)(ks * 16) * 2;   // byte offset in row
            uint32_t bh[16], bl[16];
            #pragma unroll
            for (int ni = 0; ni < 4; ++ni) {
                uint32_t ba = base + 2 * TILE_BYTES + (boff + ni * 16 * LDS_T) * 2 + ko;
                ldsm4(bh[4 * ni], bh[4 * ni + 1], bh[4 * ni + 2], bh[4 * ni + 3], ba);
                ldsm4(bl[4 * ni], bl[4 * ni + 1], bl[4 * ni + 2], bl[4 * ni + 3],
                      ba + TILE_BYTES);
            }
            #pragma unroll
            for (int mi = 0; mi < 4; ++mi) {
                uint32_t aa = base + (aoff + mi * 16 * LDS_T) * 2 + ko;
                uint32_t ah[4], al[4];
                ldsm4(ah[0], ah[1], ah[2], ah[3], aa);
                ldsm4(al[0], al[1], al[2], al[3], aa + TILE_BYTES);
                #pragma unroll
                for (int nj = 0; nj < 8; ++nj) {
                    mma16816(acc[mi][nj], ah, bh[2 * nj], bh[2 * nj + 1]);
                    mma16816(acc[mi][nj], ah, bl[2 * nj], bl[2 * nj + 1]);
                    mma16816(acc[mi][nj], al, bh[2 * nj], bh[2 * nj + 1]);
                }
            }
        }
    }

    // ---- epilogue ----
    const int g  = lane >> 2;
    const int t4 = lane & 3;
    #pragma unroll
    for (int mi = 0; mi < 4; ++mi) {
        #pragma unroll
        for (int nj = 0; nj < 8; ++nj) {
            int row = m0 + warp_m + mi * 16 + g;
            int col = n0 + warp_n + nj * 8 + 2 * t4;
            #pragma unroll
            for (int h = 0; h < 2; ++h) {
                int r = row + 8 * h;
                float v0 = acc[mi][nj][2 * h]     * alpha;
                float v1 = acc[mi][nj][2 * h + 1] * alpha;
                size_t off = z * sOz + (size_t)r * ldO + col;
                if (EPI == 0) {
                    bf16 h0, l0, h1, l1;
                    split2(v0, h0, l0);
                    split2(v1, h1, l1);
                    *(__nv_bfloat162*)(Oh + (size_t)r * ldO + col) =
                        __nv_bfloat162(h0, h1);
                    *(__nv_bfloat162*)(Ol + (size_t)r * ldO + col) =
                        __nv_bfloat162(l0, l1);
                } else if (EPI == 2) {
                    *(float2*)(outF + off) = make_float2(v0, v1);
                } else {
                    float2 rr = *(const float2*)(resid + off);
                    *(float2*)(outF + off) = make_float2(v0 + rr.x, v1 + rr.y);
                }
            }
        }
    }
}

// -------- softmax over BATCH axis, vectorized: 4 (q,k) pairs per thread ----
__global__ __launch_bounds__(256) void softmax_batch_kernel() {
    const int idx4 = (blockIdx.x * 256 + threadIdx.x) * 4;   // < S_*S_
    float4 v[B_];
    float4 m = make_float4(-3.4e38f, -3.4e38f, -3.4e38f, -3.4e38f);
    #pragma unroll
    for (int b = 0; b < B_; ++b) {
        v[b] = *(const float4*)(g_sc + (size_t)b * (S_ * S_) + idx4);
        m.x = fmaxf(m.x, v[b].x); m.y = fmaxf(m.y, v[b].y);
        m.z = fmaxf(m.z, v[b].z); m.w = fmaxf(m.w, v[b].w);
    }
    float4 s = make_float4(0.f, 0.f, 0.f, 0.f);
    #pragma unroll
    for (int b = 0; b < B_; ++b) {
        v[b].x = expf(v[b].x - m.x); s.x += v[b].x;
        v[b].y = expf(v[b].y - m.y); s.y += v[b].y;
        v[b].z = expf(v[b].z - m.z); s.z += v[b].z;
        v[b].w = expf(v[b].w - m.w); s.w += v[b].w;
    }
    float4 inv = make_float4(1.f / s.x, 1.f / s.y, 1.f / s.z, 1.f / s.w);
    #pragma unroll
    for (int b = 0; b < B_; ++b) {
        size_t o = (size_t)b * (S_ * S_) + idx4;
        bf16 h0, l0, h1, l1, h2, l2, h3, l3;
        split2(v[b].x * inv.x, h0, l0);
        split2(v[b].y * inv.y, h1, l1);
        split2(v[b].z * inv.z, h2, l2);
        split2(v[b].w * inv.w, h3, l3);
        __nv_bfloat162 hh[2] = { __nv_bfloat162(h0, h1), __nv_bfloat162(h2, h3) };
        __nv_bfloat162 ll[2] = { __nv_bfloat162(l0, l1), __nv_bfloat162(l2, l3) };
        *(uint2*)(g_wth + o) = *(const uint2*)hh;
        *(uint2*)(g_wtl + o) = *(const uint2*)ll;
    }
}

extern "C" void kernel_launch(void* const* d_in, const int* in_sizes, int n_in,
                              void* d_out, int out_size) {
    const float* x = (const float*)d_in[0];
    const float* Q = (const float*)d_in[1];
    const float* K = (const float*)d_in[2];
    const float* V = (const float*)d_in[3];
    float* out = (float*)d_out;

    float *xn, *sc;
    cudaGetSymbolAddress((void**)&xn, g_xn);
    cudaGetSymbolAddress((void**)&sc, g_sc);
    #define GET2(var, name) \
        bf16 *var##h, *var##l; \
        cudaGetSymbolAddress((void**)&var##h, name##h); \
        cudaGetSymbolAddress((void**)&var##l, name##l)
    GET2(xb, g_xb); GET2(qn, g_qn); GET2(kn, g_kn); GET2(pt, g_pt);
    GET2(vw, g_vw); GET2(yb, g_yb); GET2(vt, g_vt); GET2(wt, g_wt);

    // dynamic smem opt-in (host attribute; capture-safe)
    cudaFuncSetAttribute(mma_gemm<0>, cudaFuncAttributeMaxDynamicSharedMemorySize, SMEM_DYN);
    cudaFuncSetAttribute(mma_gemm<2>, cudaFuncAttributeMaxDynamicSharedMemorySize, SMEM_DYN);
    cudaFuncSetAttribute(mma_gemm<3>, cudaFuncAttributeMaxDynamicSharedMemorySize, SMEM_DYN);

    // 1-2) BN stats + normalize/split
    bn_stats_kernel<<<C_, 256>>>(x);
    normalize_kernel<<<dim3(S_ / 32, C_ / 32, B_), dim3(32, 8)>>>(x);

    // 3) splits: Q,K natural (for P), V transposed (for vT GEMM)
    nsplit_kernel<<<(C_ * C_) / 1024, 256>>>(Q, qnh, qnl);
    nsplit_kernel<<<(C_ * C_) / 1024, 256>>>(K, knh, knl);
    wsplit_kernel<<<dim3(16, 16), dim3(32, 8)>>>(V, vwh, vwl);

    // 4) PT[b][a] = sum_d K[b][d]*Q[a][d] / sqrt(C)
    dim3 gp(C_ / 128, C_ / 128, 1);
    mma_gemm<0><<<gp, 128, SMEM_DYN>>>(knh, knl, 0, C_, qnh, qnl, 0, C_,
                             C_, 0.04419417382415922f,
                             nullptr, nullptr, 0, C_, pth, ptl);

    // 5) y = xn@P (replaces q AND k GEMMs)
    dim3 gy(C_ / 128, BS_ / 128, 1);
    mma_gemm<0><<<gy, 128, SMEM_DYN>>>(xbh, xbl, 0, C_, pth, ptl, 0, C_,
                             C_, 1.0f, nullptr, nullptr, 0, C_, ybh, ybl);

    // 6) vT[c][s] = sum_k V^T[c][k]*xn[s][k]
    dim3 gv(BS_ / 128, C_ / 128, 1);
    mma_gemm<0><<<gv, 128, SMEM_DYN>>>(vwh, vwl, 0, C_, xbh, xbl, 0, C_,
                             C_, 1.0f, nullptr, nullptr, 0, BS_, vth, vtl);

    // 7) scores[b][s][t] = sum_d y[b][s][d]*xn[b][t][d]
    dim3 gs(S_ / 128, S_ / 128, B_);
    mma_gemm<2><<<gs, 128, SMEM_DYN>>>(ybh, ybl, (size_t)S_ * C_, C_,
                             xbh, xbl, (size_t)S_ * C_, C_,
                             C_, 1.0f,
                             sc, nullptr, (size_t)S_ * S_, S_, nullptr, nullptr);

    // 8) batch softmax + split W
    softmax_batch_kernel<<<(S_ * S_) / 1024, 256>>>();

    // 9) out[b][s][c] = sum_j W[b][s][j]*vT[c][b*S+j] + xn
    dim3 ga(C_ / 128, S_ / 128, B_);
    mma_gemm<3><<<ga, 128, SMEM_DYN>>>(wth, wtl, (size_t)S_ * S_, S_,
                             vth, vtl, (size_t)S_, BS_,
                             S_, 1.0f,
                             out, xn, (size_t)S_ * C_, C_, nullptr, nullptr);
}

// round 17
// speedup vs baseline: 1.1215x; 1.1215x over previous
#include <cuda_runtime.h>
#include <cuda_bf16.h>
#include <cstdint>

// Problem: x[16,512,32,32], Q/K/V[512,512]
#define B_ 16
#define C_ 512
#define S_ 1024
#define BS_ (B_ * S_)   // 16384

typedef __nv_bfloat16 bf16;

// ---------------- device scratch ----------------
__device__ float g_sc[B_ * S_ * S_];      // scores fp32 [B][q][k]
__device__ float g_mean[C_], g_rsig[C_];

#define PAIR(name, n) \
  __device__ __align__(16) bf16 name##h[n]; \
  __device__ __align__(16) bf16 name##l[n]
PAIR(g_xb, BS_ * C_);      // xn split       [s][c]  (also the residual: hi+lo)
PAIR(g_qn, C_ * C_);       // Q natural split [a][d]
PAIR(g_kn, C_ * C_);       // K natural split [b][d]
PAIR(g_pt, C_ * C_);       // P^T split      [b][a],  P = Q@K^T/sqrt(C)
PAIR(g_vw, C_ * C_);       // V^T split      [d][c]
PAIR(g_yb, BS_ * C_);      // y = xn@P split [b*S+s][d]
PAIR(g_vt, C_ * BS_);      // v^T split      [c][b*S+s]
PAIR(g_wt, B_ * S_ * S_);  // attn weights   [b][q][j]

// ---------------- helpers ----------------
__device__ __forceinline__ void split2(float x, bf16& h, bf16& l) {
    h = __float2bfloat16(x);
    l = __float2bfloat16(x - __bfloat162float(h));
}
__device__ __forceinline__ uint32_t smem_u32(const void* p) {
    return (uint32_t)__cvta_generic_to_shared(p);
}
__device__ __forceinline__ void cp16(uint32_t dst, const void* src) {
    asm volatile("cp.async.cg.shared.global [%0], [%1], 16;" :: "r"(dst), "l"(src));
}
__device__ __forceinline__ void ldsm4(uint32_t& r0, uint32_t& r1,
                                      uint32_t& r2, uint32_t& r3, uint32_t a) {
    asm volatile("ldmatrix.sync.aligned.m8n8.x4.shared.b16 {%0,%1,%2,%3}, [%4];"
                 : "=r"(r0), "=r"(r1), "=r"(r2), "=r"(r3) : "r"(a));
}
__device__ __forceinline__ void mma16816(float* d, const uint32_t* a,
                                         uint32_t b0, uint32_t b1) {
    asm("mma.sync.aligned.m16n8k16.row.col.f32.bf16.bf16.f32 "
        "{%0,%1,%2,%3}, {%4,%5,%6,%7}, {%8,%9}, {%0,%1,%2,%3};"
        : "+f"(d[0]), "+f"(d[1]), "+f"(d[2]), "+f"(d[3])
        : "r"(a[0]), "r"(a[1]), "r"(a[2]), "r"(a[3]), "r"(b0), "r"(b1));
}

// ---------------- BatchNorm stats ----------------
__global__ __launch_bounds__(256) void bn_stats_kernel(const float* __restrict__ x) {
    int c = blockIdx.x, t = threadIdx.x;
    float s = 0.f, ss = 0.f;
    for (int b = 0; b < B_; ++b) {
        const float* p = x + ((size_t)b * C_ + c) * S_;
        for (int i = t; i < S_; i += 256) { float v = p[i]; s += v; ss += v * v; }
    }
    #pragma unroll
    for (int o = 16; o > 0; o >>= 1) {
        s  += __shfl_down_sync(0xffffffffu, s,  o);
        ss += __shfl_down_sync(0xffffffffu, ss, o);
    }
    __shared__ float shs[8], shq[8];
    int w = t >> 5, l = t & 31;
    if (l == 0) { shs[w] = s; shq[w] = ss; }
    __syncthreads();
    if (t == 0) {
        float S = 0.f, Qq = 0.f;
        #pragma unroll
        for (int i = 0; i < 8; ++i) { S += shs[i]; Qq += shq[i]; }
        const float invN = 1.0f / (float)BS_;
        float mu = S * invN;
        g_mean[c] = mu;
        g_rsig[c] = rsqrtf(Qq * invN - mu * mu + 1e-5f);
    }
}

// ---------- normalize + transpose -> bf16 split pair ONLY (vectorized) ----------
// residual is reconstructed later as hi+lo (error 2^-17, negligible)
__global__ __launch_bounds__(256) void normalize_kernel(const float* __restrict__ x) {
    __shared__ float tile[32][33];
    int b = blockIdx.z, c0 = blockIdx.y * 32, s0 = blockIdx.x * 32;
    int tx = threadIdx.x, ty = threadIdx.y;   // (32,8)
    #pragma unroll
    for (int r = 0; r < 4; ++r)
        tile[ty + 8 * r][tx] = x[((size_t)b * C_ + c0 + ty + 8 * r) * S_ + s0 + tx];
    __syncthreads();
    int tid = ty * 32 + tx;
    int cp  = (tid & 15) * 2;     // even c_local
    int sy  = tid >> 4;           // 0..15
    float mu0 = g_mean[c0 + cp],     rs0 = g_rsig[c0 + cp];
    float mu1 = g_mean[c0 + cp + 1], rs1 = g_rsig[c0 + cp + 1];
    #pragma unroll
    for (int r = 0; r < 2; ++r) {
        int sl = sy + 16 * r;
        float v0 = (tile[cp][sl]     - mu0) * rs0;
        float v1 = (tile[cp + 1][sl] - mu1) * rs1;
        size_t idx = ((size_t)b * S_ + s0 + sl) * C_ + c0 + cp;
        bf16 h0, l0, h1, l1;
        split2(v0, h0, l0);
        split2(v1, h1, l1);
        *(__nv_bfloat162*)(g_xbh + idx) = __nv_bfloat162(h0, h1);
        *(__nv_bfloat162*)(g_xbl + idx) = __nv_bfloat162(l0, l1);
    }
}

// ---------- natural elementwise split, 4 floats/thread ----------
__global__ __launch_bounds__(256) void nsplit_kernel(
    const float* __restrict__ in, bf16* __restrict__ oh, bf16* __restrict__ ol)
{
    int i4 = (blockIdx.x * 256 + threadIdx.x) * 4;   // < C_*C_
    float4 v = *(const float4*)(in + i4);
    bf16 h0, l0, h1, l1, h2, l2, h3, l3;
    split2(v.x, h0, l0); split2(v.y, h1, l1);
    split2(v.z, h2, l2); split2(v.w, h3, l3);
    __nv_bfloat162 hh[2] = { __nv_bfloat162(h0, h1), __nv_bfloat162(h2, h3) };
    __nv_bfloat162 ll[2] = { __nv_bfloat162(l0, l1), __nv_bfloat162(l2, l3) };
    *(uint2*)(oh + i4) = *(const uint2*)hh;
    *(uint2*)(ol + i4) = *(const uint2*)ll;
}

// ---------- weight transpose + split: out[n][k] = in[k][n] (V only) ----------
__global__ __launch_bounds__(256) void wsplit_kernel(
    const float* __restrict__ in, bf16* __restrict__ oh, bf16* __restrict__ ol)
{
    __shared__ float t[32][33];
    int n0 = blockIdx.x * 32, k0 = blockIdx.y * 32;
    int tx = threadIdx.x, ty = threadIdx.y;
    #pragma unroll
    for (int r = 0; r < 4; ++r)
        t[ty + 8 * r][tx] = in[(size_t)(k0 + ty + 8 * r) * C_ + n0 + tx];
    __syncthreads();
    #pragma unroll
    for (int r = 0; r < 4; ++r) {
        size_t idx = (size_t)(n0 + ty + 8 * r) * C_ + k0 + tx;
        split2(t[tx][ty + 8 * r], oh[idx], ol[idx]);
    }
}

// ---------------------------------------------------------------------------
// Split-2 bf16 HMMA GEMM (proven R15 form): D[m][n] = alpha*sum_k A[m][k]*B[n][k]
// CTA 128x128, 4 warps of 64x64, K-chunk 16, cp.async double buffer,
// ONE __syncthreads per chunk. EPI: 0 = split-2 bf16 out; 2 = fp32*alpha;
// 3 = fp32 + residual reconstructed from bf16 pair (Rh, Rl = split residual).
// ---------------------------------------------------------------------------
#define LDS_T 24
#define TILE_BYTES (128 * LDS_T * 2)      // 6144
#define BUF_BYTES  (4 * TILE_BYTES)       // 24576

template <int EPI>
__global__ __launch_bounds__(128, 2) void mma_gemm(
    const bf16* __restrict__ Ah, const bf16* __restrict__ Al, size_t sAz, int lda,
    const bf16* __restrict__ Bh, const bf16* __restrict__ Bl, size_t sBz, int ldb,
    int K, float alpha,
    float* __restrict__ outF, size_t sOz, int ldO,
    bf16* __restrict__ Oh, bf16* __restrict__ Ol)   // EPI 0: outputs; EPI 3: residual pair
{
    __shared__ bf16 sm[2][4][128][LDS_T];   // buf, tile(Ah,Al,Bh,Bl), row, k

    const int tid = threadIdx.x, lane = tid & 31, w = tid >> 5;   // w: 0..3
    const int m0 = blockIdx.y * 128, n0 = blockIdx.x * 128, z = blockIdx.z;
    const int warp_m = (w >> 1) * 64, warp_n = (w & 1) * 64;

    const bf16* srcs[4] = { Ah + z * sAz, Al + z * sAz,
                            Bh + z * sBz, Bl + z * sBz };
    const int lld  = (w < 2) ? lda : ldb;
    const bf16* lsrc = srcs[w] + (size_t)((w < 2 ? m0 : n0) + lane) * lld;
    const uint32_t ldst = smem_u32(&sm[0][w][lane][0]);

    auto ISSUE = [&](int kc, int buf) {
        uint32_t d = ldst + buf * BUF_BYTES;
        const bf16* s0 = lsrc + kc;
        #pragma unroll
        for (int r = 0; r < 4; ++r) {
            cp16(d + r * (32 * LDS_T * 2),      s0 + (size_t)(32 * r) * lld);
            cp16(d + r * (32 * LDS_T * 2) + 16, s0 + (size_t)(32 * r) * lld + 8);
        }
        asm volatile("cp.async.commit_group;");
    };

    const uint32_t aoff = (uint32_t)((warp_m + (lane & 15)) * LDS_T + (lane >> 4) * 8);
    const uint32_t boff = (uint32_t)((warp_n + ((lane >> 4) & 1) * 8 + (lane & 7)) * LDS_T
                                     + ((lane >> 3) & 1) * 8);
    const uint32_t smb = smem_u32(sm);

    float acc[4][8][4];
    #pragma unroll
    for (int i = 0; i < 4; ++i)
        #pragma unroll
        for (int j = 0; j < 8; ++j)
            #pragma unroll
            for (int q = 0; q < 4; ++q) acc[i][j][q] = 0.f;

    const int nch = K >> 4;
    ISSUE(0, 0);
    for (int t = 0; t < nch; ++t) {
        const int buf = t & 1;
        asm volatile("cp.async.wait_group 0;");
        __syncthreads();                       // chunk t visible; buf^1 free
        if (t + 1 < nch) ISSUE((t + 1) << 4, buf ^ 1);

        const uint32_t base = smb + buf * BUF_BYTES;
        uint32_t bh[16], bl[16];
        #pragma unroll
        for (int ni = 0; ni < 4; ++ni) {
            uint32_t ba = base + 2 * TILE_BYTES + (boff + ni * 16 * LDS_T) * 2;
            ldsm4(bh[4 * ni], bh[4 * ni + 1], bh[4 * ni + 2], bh[4 * ni + 3], ba);
            ldsm4(bl[4 * ni], bl[4 * ni + 1], bl[4 * ni + 2], bl[4 * ni + 3],
                  ba + TILE_BYTES);
        }
        #pragma unroll
        for (int mi = 0; mi < 4; ++mi) {
            uint32_t aa = base + (aoff + mi * 16 * LDS_T) * 2;
            uint32_t ah[4], al[4];
            ldsm4(ah[0], ah[1], ah[2], ah[3], aa);
            ldsm4(al[0], al[1], al[2], al[3], aa + TILE_BYTES);
            #pragma unroll
            for (int nj = 0; nj < 8; ++nj) {
                mma16816(acc[mi][nj], ah, bh[2 * nj], bh[2 * nj + 1]);
                mma16816(acc[mi][nj], ah, bl[2 * nj], bl[2 * nj + 1]);
                mma16816(acc[mi][nj], al, bh[2 * nj], bh[2 * nj + 1]);
            }
        }
    }

    // ---- epilogue ----
    const int g  = lane >> 2;
    const int t4 = lane & 3;
    #pragma unroll
    for (int mi = 0; mi < 4; ++mi) {
        #pragma unroll
        for (int nj = 0; nj < 8; ++nj) {
            int row = m0 + warp_m + mi * 16 + g;
            int col = n0 + warp_n + nj * 8 + 2 * t4;
            #pragma unroll
            for (int h = 0; h < 2; ++h) {
                int r = row + 8 * h;
                float v0 = acc[mi][nj][2 * h]     * alpha;
                float v1 = acc[mi][nj][2 * h + 1] * alpha;
                size_t off = z * sOz + (size_t)r * ldO + col;
                if (EPI == 0) {
                    bf16 h0, l0, h1, l1;
                    split2(v0, h0, l0);
                    split2(v1, h1, l1);
                    *(__nv_bfloat162*)(Oh + (size_t)r * ldO + col) =
                        __nv_bfloat162(h0, h1);
                    *(__nv_bfloat162*)(Ol + (size_t)r * ldO + col) =
                        __nv_bfloat162(l0, l1);
                } else if (EPI == 2) {
                    *(float2*)(outF + off) = make_float2(v0, v1);
                } else {
                    __nv_bfloat162 rh = *(const __nv_bfloat162*)(Oh + off);
                    __nv_bfloat162 rl = *(const __nv_bfloat162*)(Ol + off);
                    v0 += __bfloat162float(rh.x) + __bfloat162float(rl.x);
                    v1 += __bfloat162float(rh.y) + __bfloat162float(rl.y);
                    *(float2*)(outF + off) = make_float2(v0, v1);
                }
            }
        }
    }
}

// -------- softmax over BATCH axis, vectorized: 4 (q,k) pairs per thread ----
__global__ __launch_bounds__(256) void softmax_batch_kernel() {
    const int idx4 = (blockIdx.x * 256 + threadIdx.x) * 4;   // < S_*S_
    float4 v[B_];
    float4 m = make_float4(-3.4e38f, -3.4e38f, -3.4e38f, -3.4e38f);
    #pragma unroll
    for (int b = 0; b < B_; ++b) {
        v[b] = *(const float4*)(g_sc + (size_t)b * (S_ * S_) + idx4);
        m.x = fmaxf(m.x, v[b].x); m.y = fmaxf(m.y, v[b].y);
        m.z = fmaxf(m.z, v[b].z); m.w = fmaxf(m.w, v[b].w);
    }
    float4 s = make_float4(0.f, 0.f, 0.f, 0.f);
    #pragma unroll
    for (int b = 0; b < B_; ++b) {
        v[b].x = expf(v[b].x - m.x); s.x += v[b].x;
        v[b].y = expf(v[b].y - m.y); s.y += v[b].y;
        v[b].z = expf(v[b].z - m.z); s.z += v[b].z;
        v[b].w = expf(v[b].w - m.w); s.w += v[b].w;
    }
    float4 inv = make_float4(1.f / s.x, 1.f / s.y, 1.f / s.z, 1.f / s.w);
    #pragma unroll
    for (int b = 0; b < B_; ++b) {
        size_t o = (size_t)b * (S_ * S_) + idx4;
        bf16 h0, l0, h1, l1, h2, l2, h3, l3;
        split2(v[b].x * inv.x, h0, l0);
        split2(v[b].y * inv.y, h1, l1);
        split2(v[b].z * inv.z, h2, l2);
        split2(v[b].w * inv.w, h3, l3);
        __nv_bfloat162 hh[2] = { __nv_bfloat162(h0, h1), __nv_bfloat162(h2, h3) };
        __nv_bfloat162 ll[2] = { __nv_bfloat162(l0, l1), __nv_bfloat162(l2, l3) };
        *(uint2*)(g_wth + o) = *(const uint2*)hh;
        *(uint2*)(g_wtl + o) = *(const uint2*)ll;
    }
}

extern "C" void kernel_launch(void* const* d_in, const int* in_sizes, int n_in,
                              void* d_out, int out_size) {
    const float* x = (const float*)d_in[0];
    const float* Q = (const float*)d_in[1];
    const float* K = (const float*)d_in[2];
    const float* V = (const float*)d_in[3];
    float* out = (float*)d_out;

    float* sc;
    cudaGetSymbolAddress((void**)&sc, g_sc);
    #define GET2(var, name) \
        bf16 *var##h, *var##l; \
        cudaGetSymbolAddress((void**)&var##h, name##h); \
        cudaGetSymbolAddress((void**)&var##l, name##l)
    GET2(xb, g_xb); GET2(qn, g_qn); GET2(kn, g_kn); GET2(pt, g_pt);
    GET2(vw, g_vw); GET2(yb, g_yb); GET2(vt, g_vt); GET2(wt, g_wt);

    // 1-2) BN stats + normalize/split (split pair only; residual = hi+lo)
    bn_stats_kernel<<<C_, 256>>>(x);
    normalize_kernel<<<dim3(S_ / 32, C_ / 32, B_), dim3(32, 8)>>>(x);

    // 3) splits: Q,K natural (for P), V transposed (for vT GEMM)
    nsplit_kernel<<<(C_ * C_) / 1024, 256>>>(Q, qnh, qnl);
    nsplit_kernel<<<(C_ * C_) / 1024, 256>>>(K, knh, knl);
    wsplit_kernel<<<dim3(16, 16), dim3(32, 8)>>>(V, vwh, vwl);

    // 4) PT[b][a] = sum_d K[b][d]*Q[a][d] / sqrt(C)
    dim3 gp(C_ / 128, C_ / 128, 1);
    mma_gemm<0><<<gp, 128>>>(knh, knl, 0, C_, qnh, qnl, 0, C_,
                             C_, 0.04419417382415922f,
                             nullptr, 0, C_, pth, ptl);

    // 5) y = xn@P (replaces q AND k GEMMs)
    dim3 gy(C_ / 128, BS_ / 128, 1);
    mma_gemm<0><<<gy, 128>>>(xbh, xbl, 0, C_, pth, ptl, 0, C_,
                             C_, 1.0f, nullptr, 0, C_, ybh, ybl);

    // 6) vT[c][s] = sum_k V^T[c][k]*xn[s][k]
    dim3 gv(BS_ / 128, C_ / 128, 1);
    mma_gemm<0><<<gv, 128>>>(vwh, vwl, 0, C_, xbh, xbl, 0, C_,
                             C_, 1.0f, nullptr, 0, BS_, vth, vtl);

    // 7) scores[b][s][t] = sum_d y[b][s][d]*xn[b][t][d]
    dim3 gs(S_ / 128, S_ / 128, B_);
    mma_gemm<2><<<gs, 128>>>(ybh, ybl, (size_t)S_ * C_, C_,
                             xbh, xbl, (size_t)S_ * C_, C_,
                             C_, 1.0f,
                             sc, (size_t)S_ * S_, S_, nullptr, nullptr);

    // 8) batch softmax + split W
    softmax_batch_kernel<<<(S_ * S_) / 1024, 256>>>();

    // 9) out[b][s][c] = sum_j W[b][s][j]*vT[c][b*S+j] + (xbh+xbl)
    dim3 ga(C_ / 128, S_ / 128, B_);
    mma_gemm<3><<<ga, 128>>>(wth, wtl, (size_t)S_ * S_, S_,
                             vth, vtl, (size_t)S_, BS_,
                             S_, 1.0f,
                             out, (size_t)S_ * C_, C_, xbh, xbl);
}